// round 6
// baseline (speedup 1.0000x reference)
#include <cuda_runtime.h>

// InteractionArch: out[b] = concat(dense[b] (128),
//        triu(k=1) of Gram([dense[b]; sparse[b].reshape(26,128)]) (351))
// B=16384, D=128, F=26, OUTW=479.
//
// One warp per sample; lane owns dims lane*4..lane*4+3 packed as 2 x f32x2.
// Register plan (target <=102 natural, cap 102 via __launch_bounds__(128,5)):
//   resident low-14 vectors packed        28 regs
//   streamed high-13 (depth-2 prefetch)    4 regs
//   p[16] chunk buffer                    16 regs
// Pair partials batched in chunks of 16; 16-element halving butterfly
// (4 select-steps + 1 select-free allreduce) leaves pair j>>1 in lane j;
// even lanes store via smem slot->triu-index table (table logic validated in R2).

#define FF    26
#define OUTW  479
#define NPAIR 351
#define NLO   14      // resident vectors: dense + sparse rows 0..12

typedef unsigned long long ull;

__device__ __forceinline__ ull mul2(ull a, ull b)
{
    ull d;
    asm("mul.rn.f32x2 %0, %1, %2;" : "=l"(d) : "l"(a), "l"(b));
    return d;
}
__device__ __forceinline__ ull fma2(ull a, ull b, ull c)
{
    ull d;
    asm("fma.rn.f32x2 %0, %1, %2, %3;" : "=l"(d) : "l"(a), "l"(b), "l"(c));
    return d;
}
__device__ __forceinline__ float hadd2(ull a)
{
    unsigned lo, hi;
    asm("mov.b64 {%0, %1}, %2;" : "=r"(lo), "=r"(hi) : "l"(a));
    return __uint_as_float(lo) + __uint_as_float(hi);
}

// dot over this lane's 4 dims: 2 packed MACs + horizontal add.
__device__ __forceinline__ float dotp(const ulonglong2 a, const ulonglong2 b)
{
    ull t = mul2(a.x, b.x);
    t = fma2(a.y, b.y, t);
    return hadd2(t);
}

// Reduce 16 lane-partial sums across 32 lanes; lane j ends holding the full
// sum of element (j>>1). 16 shuffles per 16 elements.
__device__ __forceinline__ float bfly16(float (&p)[16], const int lane)
{
#pragma unroll
    for (int s = 0; s < 4; ++s) {
        const int m   = 16 >> s;   // partner distance 16,8,4,2
        const int cnt = 8 >> s;    // live elements halve 8,4,2,1
        const bool up = (lane & m) != 0;
#pragma unroll
        for (int i = 0; i < cnt; ++i) {
            float send = up ? p[i] : p[i + cnt];
            float recv = __shfl_xor_sync(0xffffffffu, send, m);
            float keep = up ? p[i + cnt] : p[i];
            p[i] = keep + recv;
        }
    }
    // Lanes j and j^1 hold partial sums of element j>>1; fold them.
    p[0] += __shfl_xor_sync(0xffffffffu, p[0], 1);
    return p[0];
}

#define EMIT(val)                                                     \
    do {                                                              \
        p[slot] = (val);                                              \
        ++slot;                                                       \
        if (slot == 16) {                                             \
            float r = bfly16(p, lane);                                \
            if ((lane & 1) == 0)                                      \
                ob[tbl[chunk * 16 + (lane >> 1)]] = r;                \
            ++chunk;                                                  \
            slot = 0;                                                 \
        }                                                             \
    } while (0)

__global__ __launch_bounds__(128, 5)
void interact_kernel(const float* __restrict__ dense,
                     const float* __restrict__ sparse,
                     float* __restrict__ out)
{
    __shared__ int tbl[352];

    // slot -> triu output index for the emission order below (validated in R2).
    for (int s = threadIdx.x; s < NPAIR; s += blockDim.x) {
        int f, g;
        if (s < 91) {                       // phase 1: f<g within low 14
            int f0 = 0;
            while (13 * (f0 + 1) - (f0 + 1) * f0 / 2 <= s) ++f0;
            f = f0;
            g = f + 1 + (s - (13 * f - f * (f - 1) / 2));
        } else if (s < 273) {               // phase 2: g=14..26 outer, f=0..13 inner
            int t = s - 91;
            g = 14 + t / 14;
            f = t % 14;
        } else {                            // phase 3: a<b within high 13
            int t = s - 273;
            int a0 = 0;
            while (12 * (a0 + 1) - (a0 + 1) * a0 / 2 <= t) ++a0;
            int a = a0;
            int b = a + 1 + (t - (12 * a - a * (a - 1) / 2));
            f = 14 + a;
            g = 14 + b;
        }
        tbl[s] = 128 + f * 26 - f * (f - 1) / 2 + (g - f - 1);
    }
    __syncthreads();

    const int gw   = (blockIdx.x * blockDim.x + threadIdx.x) >> 5;  // sample
    const int lane = threadIdx.x & 31;

    const ulonglong2* d2 = reinterpret_cast<const ulonglong2*>(dense)  + gw * 32;
    const ulonglong2* s2 = reinterpret_cast<const ulonglong2*>(sparse) + gw * (FF * 32);
    float* ob = out + (size_t)gw * OUTW;

    // Resident low set: dense + sparse rows 0..12 (28 regs packed).
    ulonglong2 v[NLO];
    v[0] = d2[lane];
#pragma unroll
    for (int i = 1; i < NLO; ++i)
        v[i] = s2[(i - 1) * 32 + lane];

    // Depth-2 prefetch of the high stream (vectors 14,15 = rows 13,14).
    ulonglong2 u0 = s2[13 * 32 + lane];
    ulonglong2 u1 = s2[14 * 32 + lane];

    // Dense passthrough.
    {
        unsigned a, b, c, d;
        asm("mov.b64 {%0, %1}, %2;" : "=r"(a), "=r"(b) : "l"(v[0].x));
        asm("mov.b64 {%0, %1}, %2;" : "=r"(c), "=r"(d) : "l"(v[0].y));
        ob[lane * 4 + 0] = __uint_as_float(a);
        ob[lane * 4 + 1] = __uint_as_float(b);
        ob[lane * 4 + 2] = __uint_as_float(c);
        ob[lane * 4 + 3] = __uint_as_float(d);
    }

    float p[16];
    int slot = 0, chunk = 0;     // constant-folded under full unroll

    // ---- Phase 1: 91 pairs within low 14 ----
#pragma unroll
    for (int f = 0; f < NLO - 1; ++f)
#pragma unroll
        for (int g = f + 1; g < NLO; ++g)
            EMIT(dotp(v[f], v[g]));

    // ---- Phase 2: stream vectors g=14..26 (rows 13..25), 14 pairs each ----
#pragma unroll
    for (int g = NLO; g < 27; ++g) {
        ulonglong2 cur = u0;
        u0 = u1;
        if (g + 2 <= 26)
            u1 = s2[(g + 1) * 32 + lane];   // vector g+2 = row g+1
#pragma unroll
        for (int f = 0; f < NLO; ++f)
            EMIT(dotp(v[f], cur));
    }

    // Keep phase-3 reloads from being hoisted into phase 2 (reg budget).
    asm volatile("" ::: "memory");

    // ---- Phase 3: reload high 13 (L2-hot), 78 within pairs ----
    {
        ulonglong2 vh[13];
#pragma unroll
        for (int i = 0; i < 13; ++i)
            vh[i] = s2[(13 + i) * 32 + lane];
#pragma unroll
        for (int a = 0; a < 12; ++a)
#pragma unroll
            for (int b = a + 1; b < 13; ++b)
                EMIT(dotp(vh[a], vh[b]));
    }

    // ---- Tail: 351 = 21*16 + 15; pad slot 15 and flush ----
    p[15] = 0.0f;
    {
        float r = bfly16(p, lane);
        if ((lane & 1) == 0 && (lane >> 1) < 15)
            ob[tbl[21 * 16 + (lane >> 1)]] = r;
    }
}

extern "C" void kernel_launch(void* const* d_in, const int* in_sizes, int n_in,
                              void* d_out, int out_size)
{
    const float* dense  = (const float*)d_in[0];
    const float* sparse = (const float*)d_in[1];
    float* out = (float*)d_out;

    // 16384 samples, 1 warp each, 4 warps/block -> 4096 blocks, 5 blocks/SM.
    interact_kernel<<<4096, 128>>>(dense, sparse, out);
}